// round 2
// baseline (speedup 1.0000x reference)
#include <cuda_runtime.h>
#include <cstdint>

#define NODE_DIM 256
#define HIDDEN   128
#define MAX_NODES 100000

// Scratch for per-node precompute: PQ[n][0:128] = z[n]@W1a, PQ[n][128:256] = z[n]@W1b
__device__ float g_PQ[(size_t)MAX_NODES * 256];

typedef unsigned long long ull;

__device__ __forceinline__ ull pack2(float x, float y) {
    ull r; asm("mov.b64 %0, {%1, %2};" : "=l"(r) : "f"(x), "f"(y)); return r;
}
__device__ __forceinline__ ull splat2(float x) {
    ull r; asm("mov.b64 %0, {%1, %1};" : "=l"(r) : "f"(x)); return r;
}
__device__ __forceinline__ void ffma2(ull& d, ull a, ull b) {
    asm("fma.rn.f32x2 %0, %1, %2, %0;" : "+l"(d) : "l"(a), "l"(b));
}

union U4 { float4 f; ull u[2]; };
union U2 { float2 f; ull u; };

// ---------------------------------------------------------------------------
// Phase 1: PQ = z (M x 256) @ B (256 x 256)
//   B[:,0:128]   = W1[0:256, :]    (W1a)
//   B[:,128:256] = W1[256:512, :]  (W1b)
// Tiled SGEMM, BM=128 BN=128 BK=16, 256 threads, 8x8 micro-tile, f32x2 FMAs.
// ---------------------------------------------------------------------------
#define BM 128
#define BN 128
#define BK 16

__global__ __launch_bounds__(256, 2) void gemm_pq_kernel(
    const float* __restrict__ z, const float* __restrict__ W1, int M)
{
    __shared__ float As[BK][BM];   // transposed A tile: As[k][m]
    __shared__ float Bs[BK][BN];

    const int bn   = blockIdx.x;          // 0 or 1 (which 128-col half)
    const int row0 = blockIdx.y * BM;
    const int tid  = threadIdx.x;
    const int tx   = tid & 15;            // col group: cols tx*8 .. tx*8+7
    const int ty   = tid >> 4;            // row group: rows ty*8 .. ty*8+7
    const int wrow0 = bn * 256;           // W1 row offset for this half

    ull acc[8][4];
    #pragma unroll
    for (int i = 0; i < 8; i++)
        #pragma unroll
        for (int j = 0; j < 4; j++) acc[i][j] = 0ull;

    for (int kc = 0; kc < NODE_DIM; kc += BK) {
        // Load A tile (coalesced float4 along k, scattered transposed into As)
        #pragma unroll
        for (int l = 0; l < 2; l++) {
            int f  = tid + l * 256;        // 0..511 float4 slots
            int am = f >> 2;               // 0..127
            int ak = (f & 3) * 4;          // 0,4,8,12
            float4 v = make_float4(0.f, 0.f, 0.f, 0.f);
            int row = row0 + am;
            if (row < M)
                v = *(const float4*)(z + (size_t)row * NODE_DIM + kc + ak);
            As[ak + 0][am] = v.x; As[ak + 1][am] = v.y;
            As[ak + 2][am] = v.z; As[ak + 3][am] = v.w;
        }
        // Load B tile (coalesced, conflict-free STS.128)
        #pragma unroll
        for (int l = 0; l < 2; l++) {
            int f   = tid + l * 256;
            int bk  = f >> 5;              // 0..15
            int bc  = (f & 31) * 4;        // 0..124
            float4 v = *(const float4*)(W1 + (size_t)(wrow0 + kc + bk) * HIDDEN + bc);
            *(float4*)(&Bs[bk][bc]) = v;
        }
        __syncthreads();

        #pragma unroll
        for (int kk = 0; kk < BK; kk++) {
            U4 b0, b1r;
            b0.f  = *(const float4*)(&Bs[kk][tx * 8]);
            b1r.f = *(const float4*)(&Bs[kk][tx * 8 + 4]);
            float4 a0 = *(const float4*)(&As[kk][ty * 8]);
            float4 a1 = *(const float4*)(&As[kk][ty * 8 + 4]);
            float av[8] = {a0.x, a0.y, a0.z, a0.w, a1.x, a1.y, a1.z, a1.w};
            #pragma unroll
            for (int i = 0; i < 8; i++) {
                ull as = splat2(av[i]);
                ffma2(acc[i][0], as, b0.u[0]);
                ffma2(acc[i][1], as, b0.u[1]);
                ffma2(acc[i][2], as, b1r.u[0]);
                ffma2(acc[i][3], as, b1r.u[1]);
            }
        }
        __syncthreads();
    }

    #pragma unroll
    for (int i = 0; i < 8; i++) {
        int row = row0 + ty * 8 + i;
        if (row < M) {
            float* dst = g_PQ + (size_t)row * 256 + bn * BN + tx * 8;
            U4 o0; o0.u[0] = acc[i][0]; o0.u[1] = acc[i][1];
            U4 o1; o1.u[0] = acc[i][2]; o1.u[1] = acc[i][3];
            *(float4*)dst       = o0.f;
            *(float4*)(dst + 4) = o1.f;
        }
    }
}

// ---------------------------------------------------------------------------
// Phase 2: per-edge. 2 warps per edge (warp p covers cols p*64..p*64+63,
// 2 cols per lane). W1c (32x128) held in registers, packed over i-pairs for
// f32x2. ea row read as uniform float4 broadcasts. Pair-reduce via named
// barrier + parity-double-buffered smem slots.
// NOTE: edge_label_index is int32 (JAX x64 disabled canonicalizes int64->int32).
// ---------------------------------------------------------------------------
__global__ __launch_bounds__(256, 2) void edge_kernel(
    const int* __restrict__ eli, const float* __restrict__ ea,
    const float* __restrict__ W1, const float* __restrict__ b1,
    const float* __restrict__ W2, const float* __restrict__ b2,
    float* __restrict__ out, int E)
{
    __shared__ float sred[2][8];

    const int tid  = threadIdx.x;
    const int lane = tid & 31;
    const int wid  = tid >> 5;      // 0..7
    const int pair = wid >> 1;      // 0..3 (edge slot within block)
    const int p    = wid & 1;       // which half of the 128 cols
    const int j0   = p * 64 + lane * 2;

    // W1c columns j0, j0+1, packed as (row 2i, row 2i+1) pairs -> 32 b64 regs
    ull wa[16], wb[16];
    #pragma unroll
    for (int ip = 0; ip < 16; ip++) {
        const float* r0 = W1 + (size_t)(512 + 2 * ip) * HIDDEN;
        const float* r1 = W1 + (size_t)(513 + 2 * ip) * HIDDEN;
        wa[ip] = pack2(r0[j0],     r1[j0]);
        wb[ip] = pack2(r0[j0 + 1], r1[j0 + 1]);
    }
    float2 bb  = *(const float2*)(b1 + j0);
    float2 wo  = *(const float2*)(W2 + j0);
    float  b2v = b2[0];

    int it = 0;
    for (long e = (long)blockIdx.x * 4 + pair; e < E;
         e += (long)gridDim.x * 4, it++) {
        int s = eli[e];
        int d = eli[(long)E + e];
        float2 ps = *(const float2*)(g_PQ + (size_t)s * 256 + j0);         // P[src]
        float2 pd = *(const float2*)(g_PQ + (size_t)d * 256 + 128 + j0);   // Q[dst]

        // acc = (even-i partial incl. base, odd-i partial)
        ull acc0 = pack2(ps.x + pd.x + bb.x, 0.f);
        ull acc1 = pack2(ps.y + pd.y + bb.y, 0.f);

        const float4* eap = (const float4*)(ea + (size_t)e * 32);
        #pragma unroll
        for (int q = 0; q < 8; q++) {
            U4 v; v.f = __ldg(eap + q);   // uniform broadcast across warp
            ffma2(acc0, v.u[0], wa[2 * q]);
            ffma2(acc0, v.u[1], wa[2 * q + 1]);
            ffma2(acc1, v.u[0], wb[2 * q]);
            ffma2(acc1, v.u[1], wb[2 * q + 1]);
        }

        U2 a0; a0.u = acc0;
        U2 a1; a1.u = acc1;
        float h0 = fmaxf(a0.f.x + a0.f.y, 0.f);
        float h1 = fmaxf(a1.f.x + a1.f.y, 0.f);
        float part = h0 * wo.x + h1 * wo.y;

        #pragma unroll
        for (int o = 16; o > 0; o >>= 1)
            part += __shfl_xor_sync(0xffffffffu, part, o);

        int par = it & 1;
        if (lane == 0) sred[par][wid] = part;
        asm volatile("bar.sync %0, 64;" :: "r"(pair + 1) : "memory");
        if (p == 0 && lane == 0)
            out[e] = sred[par][wid] + sred[par][wid + 1] + b2v;
    }
}

// ---------------------------------------------------------------------------
extern "C" void kernel_launch(void* const* d_in, const int* in_sizes, int n_in,
                              void* d_out, int out_size) {
    const float* z   = (const float*)d_in[0];
    const int*   eli = (const int*)d_in[1];      // int32 (JAX canonicalized)
    const float* ea  = (const float*)d_in[2];
    const float* W1  = (const float*)d_in[3];
    const float* b1  = (const float*)d_in[4];
    const float* W2  = (const float*)d_in[5];
    const float* b2  = (const float*)d_in[6];
    float* out = (float*)d_out;

    int M = in_sizes[0] / NODE_DIM;   // 100000
    int E = out_size;                 // 1000000

    dim3 g1(2, (M + BM - 1) / BM);
    gemm_pq_kernel<<<g1, 256>>>(z, W1, M);

    edge_kernel<<<304, 256>>>(eli, ea, W1, b1, W2, b2, out, E);
}

// round 3
// speedup vs baseline: 1.6975x; 1.6975x over previous
#include <cuda_runtime.h>
#include <cstdint>

#define NODE_DIM 256
#define HIDDEN   128
#define MAX_NODES 100000

// Scratch: PQ[n][0:128] = z[n]@W1a, PQ[n][128:256] = z[n]@W1b
__device__ float g_PQ[(size_t)MAX_NODES * 256];

typedef unsigned long long ull;

__device__ __forceinline__ ull pack2(float x, float y) {
    ull r; asm("mov.b64 %0, {%1, %2};" : "=l"(r) : "f"(x), "f"(y)); return r;
}
__device__ __forceinline__ ull splat2(float x) {
    ull r; asm("mov.b64 %0, {%1, %1};" : "=l"(r) : "f"(x)); return r;
}
__device__ __forceinline__ void ffma2(ull& d, ull a, ull b) {
    asm("fma.rn.f32x2 %0, %1, %2, %0;" : "+l"(d) : "l"(a), "l"(b));
}

union U4 { float4 f; ull u[2]; };
union U2 { float2 f; ull u; };

// ---------------------------------------------------------------------------
// Phase 1: PQ = z (M x 256) @ [W1a | W1b] (256 x 256). SGEMM, f32x2.
// ---------------------------------------------------------------------------
#define BM 128
#define BN 128
#define BK 16

__global__ __launch_bounds__(256, 2) void gemm_pq_kernel(
    const float* __restrict__ z, const float* __restrict__ W1, int M)
{
    __shared__ float As[BK][BM];
    __shared__ float Bs[BK][BN];

    const int bn   = blockIdx.x;
    const int row0 = blockIdx.y * BM;
    const int tid  = threadIdx.x;
    const int tx   = tid & 15;
    const int ty   = tid >> 4;
    const int wrow0 = bn * 256;

    ull acc[8][4];
    #pragma unroll
    for (int i = 0; i < 8; i++)
        #pragma unroll
        for (int j = 0; j < 4; j++) acc[i][j] = 0ull;

    for (int kc = 0; kc < NODE_DIM; kc += BK) {
        #pragma unroll
        for (int l = 0; l < 2; l++) {
            int f  = tid + l * 256;
            int am = f >> 2;
            int ak = (f & 3) * 4;
            float4 v = make_float4(0.f, 0.f, 0.f, 0.f);
            int row = row0 + am;
            if (row < M)
                v = *(const float4*)(z + (size_t)row * NODE_DIM + kc + ak);
            As[ak + 0][am] = v.x; As[ak + 1][am] = v.y;
            As[ak + 2][am] = v.z; As[ak + 3][am] = v.w;
        }
        #pragma unroll
        for (int l = 0; l < 2; l++) {
            int f   = tid + l * 256;
            int bk  = f >> 5;
            int bc  = (f & 31) * 4;
            float4 v = *(const float4*)(W1 + (size_t)(wrow0 + kc + bk) * HIDDEN + bc);
            *(float4*)(&Bs[bk][bc]) = v;
        }
        __syncthreads();

        #pragma unroll
        for (int kk = 0; kk < BK; kk++) {
            U4 b0, b1r;
            b0.f  = *(const float4*)(&Bs[kk][tx * 8]);
            b1r.f = *(const float4*)(&Bs[kk][tx * 8 + 4]);
            float4 a0 = *(const float4*)(&As[kk][ty * 8]);
            float4 a1 = *(const float4*)(&As[kk][ty * 8 + 4]);
            float av[8] = {a0.x, a0.y, a0.z, a0.w, a1.x, a1.y, a1.z, a1.w};
            #pragma unroll
            for (int i = 0; i < 8; i++) {
                ull as = splat2(av[i]);
                ffma2(acc[i][0], as, b0.u[0]);
                ffma2(acc[i][1], as, b0.u[1]);
                ffma2(acc[i][2], as, b1r.u[0]);
                ffma2(acc[i][3], as, b1r.u[1]);
            }
        }
        __syncthreads();
    }

    #pragma unroll
    for (int i = 0; i < 8; i++) {
        int row = row0 + ty * 8 + i;
        if (row < M) {
            float* dst = g_PQ + (size_t)row * 256 + bn * BN + tx * 8;
            U4 o0; o0.u[0] = acc[i][0]; o0.u[1] = acc[i][1];
            U4 o1; o1.u[0] = acc[i][2]; o1.u[1] = acc[i][3];
            *(float4*)dst       = o0.f;
            *(float4*)(dst + 4) = o1.f;
        }
    }
}

// ---------------------------------------------------------------------------
// Phase 2: edge phase as tiled GEMM + fused gather epilogue.
// Tile = 64 edges x 128 hidden. 256 threads: tc = tid&15 (cols tc*8..tc*8+7),
// tg = tid>>4 (edges tg*4..tg*4+3). W1c in smem (loaded once per block),
// EA tile transposed in smem. Epilogue: gather P/Q (float4, coalesced),
// relu, dot W2, 4-stage shfl reduce over 16 lanes.
// ---------------------------------------------------------------------------
#define TE 64

__global__ __launch_bounds__(256, 2) void edge_kernel(
    const int* __restrict__ eli, const float* __restrict__ ea,
    const float* __restrict__ W1, const float* __restrict__ b1,
    const float* __restrict__ W2, const float* __restrict__ b2,
    float* __restrict__ out, int E)
{
    __shared__ float sW[32][128];     // W1c
    __shared__ float sEA[32][68];     // transposed EA tile [k][e], padded
    __shared__ int   sS[TE];
    __shared__ int   sD[TE];

    const int tid = threadIdx.x;
    const int tc  = tid & 15;         // col group
    const int tg  = tid >> 4;         // edge group (0..15)

    // Load W1c (rows 512..543 of W1) into smem, coalesced float4
    #pragma unroll
    for (int l = 0; l < 4; l++) {
        int f = tid + l * 256;        // 0..1023
        int r = f >> 5;               // 0..31
        int c = (f & 31) * 4;         // 0..124
        *(float4*)(&sW[r][c]) = *(const float4*)(W1 + (size_t)(512 + r) * HIDDEN + c);
    }

    const float4 b1a = *(const float4*)(b1 + tc * 8);
    const float4 b1b = *(const float4*)(b1 + tc * 8 + 4);
    const float4 w2a = *(const float4*)(W2 + tc * 8);
    const float4 w2b = *(const float4*)(W2 + tc * 8 + 4);
    const float  b2v = b2[0];

    const int ntiles = (E + TE - 1) / TE;
    const int el  = tid >> 2;         // 0..63 : edge slot for EA load
    const int prt = tid & 3;          // 0..3  : k-chunk part for EA load

    for (int tile = blockIdx.x; tile < ntiles; tile += gridDim.x) {
        const int e0 = tile * TE;

        __syncthreads();   // previous tile's readers done before overwrite

        // indices
        if (tid < TE) {
            int e = e0 + tid;
            sS[tid] = (e < E) ? eli[e] : 0;
        } else if (tid < 2 * TE) {
            int e = e0 + (tid - TE);
            sD[tid - TE] = (e < E) ? eli[(size_t)E + e] : 0;
        }

        // EA tile, transposed into sEA[k][e]
        {
            int e = e0 + el;
            #pragma unroll
            for (int h = 0; h < 2; h++) {
                int c4 = prt + h * 4;           // float4 chunk index (k = c4*4..c4*4+3)
                float4 v = make_float4(0.f, 0.f, 0.f, 0.f);
                if (e < E)
                    v = *(const float4*)(ea + (size_t)e * 32 + c4 * 4);
                sEA[c4 * 4 + 0][el] = v.x;
                sEA[c4 * 4 + 1][el] = v.y;
                sEA[c4 * 4 + 2][el] = v.z;
                sEA[c4 * 4 + 3][el] = v.w;
            }
        }
        __syncthreads();

        // --- GEMM: 4 edges x 8 cols per thread, f32x2 over col pairs ---
        ull acc[4][4];
        #pragma unroll
        for (int i = 0; i < 4; i++)
            #pragma unroll
            for (int j = 0; j < 4; j++) acc[i][j] = 0ull;

        #pragma unroll 8
        for (int k = 0; k < 32; k++) {
            U4 blo, bhi;
            blo.f = *(const float4*)(&sW[k][tc * 8]);
            bhi.f = *(const float4*)(&sW[k][tc * 8 + 4]);
            float4 av = *(const float4*)(&sEA[k][tg * 4]);
            float a4[4] = {av.x, av.y, av.z, av.w};
            #pragma unroll
            for (int i = 0; i < 4; i++) {
                ull s = splat2(a4[i]);
                ffma2(acc[i][0], s, blo.u[0]);
                ffma2(acc[i][1], s, blo.u[1]);
                ffma2(acc[i][2], s, bhi.u[0]);
                ffma2(acc[i][3], s, bhi.u[1]);
            }
        }

        // --- Epilogue: gather P/Q, relu, dot W2, reduce over 16 lanes ---
        #pragma unroll
        for (int i = 0; i < 4; i++) {
            int eloc = tg * 4 + i;
            int e    = e0 + eloc;
            int s    = sS[eloc];
            int d    = sD[eloc];
            const float* pr = g_PQ + (size_t)s * 256 + tc * 8;
            const float* qr = g_PQ + (size_t)d * 256 + 128 + tc * 8;
            float4 pa = __ldg((const float4*)pr);
            float4 pb = __ldg((const float4*)(pr + 4));
            float4 qa = __ldg((const float4*)qr);
            float4 qb = __ldg((const float4*)(qr + 4));

            U2 x0, x1, x2, x3;
            x0.u = acc[i][0]; x1.u = acc[i][1];
            x2.u = acc[i][2]; x3.u = acc[i][3];

            float h0 = fmaxf(x0.f.x + pa.x + qa.x + b1a.x, 0.f);
            float h1 = fmaxf(x0.f.y + pa.y + qa.y + b1a.y, 0.f);
            float h2 = fmaxf(x1.f.x + pa.z + qa.z + b1a.z, 0.f);
            float h3 = fmaxf(x1.f.y + pa.w + qa.w + b1a.w, 0.f);
            float h4 = fmaxf(x2.f.x + pb.x + qb.x + b1b.x, 0.f);
            float h5 = fmaxf(x2.f.y + pb.y + qb.y + b1b.y, 0.f);
            float h6 = fmaxf(x3.f.x + pb.z + qb.z + b1b.z, 0.f);
            float h7 = fmaxf(x3.f.y + pb.w + qb.w + b1b.w, 0.f);

            float part = h0 * w2a.x + h1 * w2a.y + h2 * w2a.z + h3 * w2a.w
                       + h4 * w2b.x + h5 * w2b.y + h6 * w2b.z + h7 * w2b.w;

            part += __shfl_xor_sync(0xffffffffu, part, 8);
            part += __shfl_xor_sync(0xffffffffu, part, 4);
            part += __shfl_xor_sync(0xffffffffu, part, 2);
            part += __shfl_xor_sync(0xffffffffu, part, 1);

            if (tc == 0 && e < E)
                out[e] = part + b2v;
        }
    }
}

// ---------------------------------------------------------------------------
extern "C" void kernel_launch(void* const* d_in, const int* in_sizes, int n_in,
                              void* d_out, int out_size) {
    const float* z   = (const float*)d_in[0];
    const int*   eli = (const int*)d_in[1];      // int32 (JAX canonicalized)
    const float* ea  = (const float*)d_in[2];
    const float* W1  = (const float*)d_in[3];
    const float* b1  = (const float*)d_in[4];
    const float* W2  = (const float*)d_in[5];
    const float* b2  = (const float*)d_in[6];
    float* out = (float*)d_out;

    int M = in_sizes[0] / NODE_DIM;   // 100000
    int E = out_size;                 // 1000000

    dim3 g1(2, (M + BM - 1) / BM);
    gemm_pq_kernel<<<g1, 256>>>(z, W1, M);

    int ntiles = (E + TE - 1) / TE;
    int nblk = ntiles < 1184 ? ntiles : 1184;
    edge_kernel<<<nblk, 256>>>(eli, ea, W1, b1, W2, b2, out, E);
}

// round 5
// speedup vs baseline: 1.9404x; 1.1431x over previous
#include <cuda_runtime.h>
#include <cuda_bf16.h>
#include <cstdint>

#define NODE_DIM 256
#define HIDDEN   128
#define MAX_NODES 100000

// ---------------- device scratch ----------------
__device__ float         g_PQ [(size_t)MAX_NODES * 256];   // P|Q per node
__device__ __nv_bfloat16 g_zhi[(size_t)MAX_NODES * 256];
__device__ __nv_bfloat16 g_zlo[(size_t)MAX_NODES * 256];
__device__ __nv_bfloat16 g_Bhi[256 * 256];                  // B[n][k] = W1ab[k][n]
__device__ __nv_bfloat16 g_Blo[256 * 256];

typedef unsigned long long ull;

// ---------------- fp32x2 helpers (edge kernel) ----------------
__device__ __forceinline__ ull splat2(float x) {
    ull r; asm("mov.b64 %0, {%1, %1};" : "=l"(r) : "f"(x)); return r;
}
__device__ __forceinline__ void ffma2(ull& d, ull a, ull b) {
    asm("fma.rn.f32x2 %0, %1, %2, %0;" : "+l"(d) : "l"(a), "l"(b));
}
union U4 { float4 f; ull u[2]; };
union U2 { float2 f; ull u; };

// ---------------- warp-mma helpers (baseline PTX, no 'a' features) --------
__device__ __forceinline__ uint32_t smem_u32(const void* p) {
    uint32_t a;
    asm("{ .reg .u64 t; cvta.to.shared.u64 t, %1; cvt.u32.u64 %0, t; }" : "=r"(a) : "l"(p));
    return a;
}
__device__ __forceinline__ void ldsm4(uint32_t* r, uint32_t addr) {
    asm volatile("ldmatrix.sync.aligned.m8n8.x4.shared.b16 {%0,%1,%2,%3}, [%4];"
        : "=r"(r[0]), "=r"(r[1]), "=r"(r[2]), "=r"(r[3]) : "r"(addr));
}
__device__ __forceinline__ void mma_bf16(float* d, const uint32_t* a, const uint32_t* b) {
    asm volatile("mma.sync.aligned.m16n8k16.row.col.f32.bf16.bf16.f32 "
        "{%0,%1,%2,%3}, {%4,%5,%6,%7}, {%8,%9}, {%0,%1,%2,%3};"
        : "+f"(d[0]), "+f"(d[1]), "+f"(d[2]), "+f"(d[3])
        : "r"(a[0]), "r"(a[1]), "r"(a[2]), "r"(a[3]), "r"(b[0]), "r"(b[1]));
}

#define SW128(o) ((o) ^ (((o) >> 3) & 0x70))

// ---------------------------------------------------------------------------
// Convert kernels: fp32 -> bf16 hi/lo split
// ---------------------------------------------------------------------------
union BP4 { __nv_bfloat16 b[4]; uint2 u; };

__global__ void conv_z_kernel(const float* __restrict__ z, int n) {
    int stride = gridDim.x * blockDim.x;
    for (int i = blockIdx.x * blockDim.x + threadIdx.x; i * 4 < n; i += stride) {
        float4 v = *(const float4*)(z + (size_t)i * 4);
        float x[4] = {v.x, v.y, v.z, v.w};
        BP4 hi, lo;
        #pragma unroll
        for (int t = 0; t < 4; t++) {
            hi.b[t] = __float2bfloat16(x[t]);
            lo.b[t] = __float2bfloat16(x[t] - __bfloat162float(hi.b[t]));
        }
        *(uint2*)(g_zhi + (size_t)i * 4) = hi.u;
        *(uint2*)(g_zlo + (size_t)i * 4) = lo.u;
    }
}

// B[n][k]: n<128 -> W1[k][n]; n>=128 -> W1[256+k][n-128]
__global__ void conv_B_kernel(const float* __restrict__ W1) {
    int idx = blockIdx.x * blockDim.x + threadIdx.x;   // 0..65535
    int n = idx >> 8, k = idx & 255;
    float w = (n < HIDDEN) ? W1[(size_t)k * HIDDEN + n]
                           : W1[(size_t)(256 + k) * HIDDEN + (n - HIDDEN)];
    __nv_bfloat16 hi = __float2bfloat16(w);
    __nv_bfloat16 lo = __float2bfloat16(w - __bfloat162float(hi));
    g_Bhi[idx] = hi;
    g_Blo[idx] = lo;
}

// ---------------------------------------------------------------------------
// Phase 1: PQ = z @ [W1a|W1b] via mma.sync bf16 3-term split.
// CTA: 128 rows, 8 warps (warp = one m16 tile x 128 cols). Two N-half passes,
// K chunked by 64. SW128 smem, ldmatrix fragment loads.
// ---------------------------------------------------------------------------
#define SA_HI 0
#define SA_LO 16384
#define SB_HI 32768
#define SB_LO 49152
#define GSMEM 65536

__global__ __launch_bounds__(256, 2) void gemm_tc_kernel(int M) {
    extern __shared__ char smem[];
    const uint32_t sb = smem_u32(smem);
    const int tid  = threadIdx.x;
    const int warp = tid >> 5;
    const int lane = tid & 31;
    const int m0   = blockIdx.x * 128;

    // ldmatrix per-thread address components
    const uint32_t a_row  = warp * 16 + ((lane >> 3) & 1) * 8 + (lane & 7);
    const uint32_t a_koff = (lane >> 4) * 16;
    const uint32_t b_rowi = ((lane >> 4) & 1) * 8 + (lane & 7);
    const uint32_t b_koff = ((lane >> 3) & 1) * 16;

    #pragma unroll 1
    for (int nh = 0; nh < 2; nh++) {
        float acc[16][4];
        #pragma unroll
        for (int i = 0; i < 16; i++)
            #pragma unroll
            for (int j = 0; j < 4; j++) acc[i][j] = 0.f;

        #pragma unroll 1
        for (int ch = 0; ch < 4; ch++) {
            const int kc = ch * 64;
            __syncthreads();
            // A tiles: 128 rows x 64 bf16, SW128 rows of 128B
            #pragma unroll
            for (int j = 0; j < 4; j++) {
                int id = j * 256 + tid;        // 0..1023
                int r = id >> 3, c = id & 7;
                uint4 vh = make_uint4(0, 0, 0, 0), vl = make_uint4(0, 0, 0, 0);
                int row = m0 + r;
                if (row < M) {
                    size_t off = (size_t)row * 256 + kc + c * 8;
                    vh = *(const uint4*)(g_zhi + off);
                    vl = *(const uint4*)(g_zlo + off);
                }
                uint32_t so = SW128((uint32_t)(r * 128 + c * 16));
                *(uint4*)(smem + SA_HI + so) = vh;
                *(uint4*)(smem + SA_LO + so) = vl;
            }
            // B tiles: 128 n-rows (this half) x 64 bf16
            #pragma unroll
            for (int j = 0; j < 4; j++) {
                int id = j * 256 + tid;
                int r = id >> 3, c = id & 7;
                size_t off = (size_t)(nh * 128 + r) * 256 + kc + c * 8;
                uint4 vh = *(const uint4*)(g_Bhi + off);
                uint4 vl = *(const uint4*)(g_Blo + off);
                uint32_t so = SW128((uint32_t)(r * 128 + c * 16));
                *(uint4*)(smem + SB_HI + so) = vh;
                *(uint4*)(smem + SB_LO + so) = vl;
            }
            __syncthreads();

            #pragma unroll
            for (int kt = 0; kt < 4; kt++) {
                uint32_t ah[4], al[4];
                uint32_t aoff = SW128(a_row * 128 + kt * 32 + a_koff);
                ldsm4(ah, sb + SA_HI + aoff);
                ldsm4(al, sb + SA_LO + aoff);
                #pragma unroll
                for (int ntp = 0; ntp < 8; ntp++) {
                    uint32_t boff = SW128((ntp * 16 + b_rowi) * 128 + kt * 32 + b_koff);
                    uint32_t bh[4], bl[4];
                    ldsm4(bh, sb + SB_HI + boff);
                    ldsm4(bl, sb + SB_LO + boff);
                    mma_bf16(acc[2 * ntp],     ah, bh);
                    mma_bf16(acc[2 * ntp],     ah, bl);
                    mma_bf16(acc[2 * ntp],     al, bh);
                    mma_bf16(acc[2 * ntp + 1], ah, bh + 2);
                    mma_bf16(acc[2 * ntp + 1], ah, bl + 2);
                    mma_bf16(acc[2 * ntp + 1], al, bh + 2);
                }
            }
        }

        // Epilogue: write accumulators to g_PQ
        const int r0 = m0 + warp * 16 + (lane >> 2);
        const int c0 = nh * 128 + 2 * (lane & 3);
        #pragma unroll
        for (int nt = 0; nt < 16; nt++) {
            int n0 = c0 + nt * 8;
            if (r0 < M)
                *(float2*)(g_PQ + (size_t)r0 * 256 + n0) =
                    make_float2(acc[nt][0], acc[nt][1]);
            if (r0 + 8 < M)
                *(float2*)(g_PQ + (size_t)(r0 + 8) * 256 + n0) =
                    make_float2(acc[nt][2], acc[nt][3]);
        }
        __syncthreads();
    }
}

// ---------------------------------------------------------------------------
// Phase 2: edge tiles 128 edges x 128 cols; thread = 8 edges x 8 cols.
// ---------------------------------------------------------------------------
#define TE 128

__global__ __launch_bounds__(256, 2) void edge_kernel(
    const int* __restrict__ eli, const float* __restrict__ ea,
    const float* __restrict__ W1, const float* __restrict__ b1,
    const float* __restrict__ W2, const float* __restrict__ b2,
    float* __restrict__ out, int E)
{
    __shared__ float sW[32][128];
    __shared__ float sEA[32][132];
    __shared__ int   sS[TE];
    __shared__ int   sD[TE];

    const int tid = threadIdx.x;
    const int tc  = tid & 15;          // col group: cols tc*8..tc*8+7
    const int tg  = tid >> 4;          // edge group: edges tg*8..tg*8+7

    #pragma unroll
    for (int l = 0; l < 4; l++) {
        int f = tid + l * 256;
        int r = f >> 5, c = (f & 31) * 4;
        *(float4*)(&sW[r][c]) = *(const float4*)(W1 + (size_t)(512 + r) * HIDDEN + c);
    }

    const float4 b1a = *(const float4*)(b1 + tc * 8);
    const float4 b1b = *(const float4*)(b1 + tc * 8 + 4);
    const float4 w2a = *(const float4*)(W2 + tc * 8);
    const float4 w2b = *(const float4*)(W2 + tc * 8 + 4);
    const float  b2v = b2[0];

    const int ntiles = (E + TE - 1) / TE;

    for (int tile = blockIdx.x; tile < ntiles; tile += gridDim.x) {
        const int e0 = tile * TE;
        __syncthreads();

        if (tid < TE) {
            int e = e0 + tid;
            sS[tid] = (e < E) ? eli[e] : 0;
        } else {
            int e = e0 + (tid - TE);
            sD[tid - TE] = (e < E) ? eli[(size_t)E + e] : 0;
        }

        #pragma unroll
        for (int j = 0; j < 4; j++) {
            int id = j * 256 + tid;            // 0..1023
            int el = id >> 3, c4 = id & 7;
            int e  = e0 + el;
            float4 v = make_float4(0.f, 0.f, 0.f, 0.f);
            if (e < E) v = *(const float4*)(ea + (size_t)e * 32 + c4 * 4);
            sEA[c4 * 4 + 0][el] = v.x;
            sEA[c4 * 4 + 1][el] = v.y;
            sEA[c4 * 4 + 2][el] = v.z;
            sEA[c4 * 4 + 3][el] = v.w;
        }
        __syncthreads();

        ull acc[8][4];
        #pragma unroll
        for (int i = 0; i < 8; i++)
            #pragma unroll
            for (int j = 0; j < 4; j++) acc[i][j] = 0ull;

        #pragma unroll 8
        for (int k = 0; k < 32; k++) {
            U4 blo, bhi;
            blo.f = *(const float4*)(&sW[k][tc * 8]);
            bhi.f = *(const float4*)(&sW[k][tc * 8 + 4]);
            float4 a0 = *(const float4*)(&sEA[k][tg * 8]);
            float4 a1 = *(const float4*)(&sEA[k][tg * 8 + 4]);
            float a8[8] = {a0.x, a0.y, a0.z, a0.w, a1.x, a1.y, a1.z, a1.w};
            #pragma unroll
            for (int i = 0; i < 8; i++) {
                ull s = splat2(a8[i]);
                ffma2(acc[i][0], s, blo.u[0]);
                ffma2(acc[i][1], s, blo.u[1]);
                ffma2(acc[i][2], s, bhi.u[0]);
                ffma2(acc[i][3], s, bhi.u[1]);
            }
        }

        #pragma unroll 2
        for (int i = 0; i < 8; i++) {
            int eloc = tg * 8 + i;
            int e    = e0 + eloc;
            int s    = sS[eloc];
            int d    = sD[eloc];
            const float* pr = g_PQ + (size_t)s * 256 + tc * 8;
            const float* qr = g_PQ + (size_t)d * 256 + 128 + tc * 8;
            float4 pa = __ldg((const float4*)pr);
            float4 pb = __ldg((const float4*)(pr + 4));
            float4 qa = __ldg((const float4*)qr);
            float4 qb = __ldg((const float4*)(qr + 4));

            U2 x0, x1, x2, x3;
            x0.u = acc[i][0]; x1.u = acc[i][1];
            x2.u = acc[i][2]; x3.u = acc[i][3];

            float h0 = fmaxf(x0.f.x + pa.x + qa.x + b1a.x, 0.f);
            float h1 = fmaxf(x0.f.y + pa.y + qa.y + b1a.y, 0.f);
            float h2 = fmaxf(x1.f.x + pa.z + qa.z + b1a.z, 0.f);
            float h3 = fmaxf(x1.f.y + pa.w + qa.w + b1a.w, 0.f);
            float h4 = fmaxf(x2.f.x + pb.x + qb.x + b1b.x, 0.f);
            float h5 = fmaxf(x2.f.y + pb.y + qb.y + b1b.y, 0.f);
            float h6 = fmaxf(x3.f.x + pb.z + qb.z + b1b.z, 0.f);
            float h7 = fmaxf(x3.f.y + pb.w + qb.w + b1b.w, 0.f);

            float part = h0 * w2a.x + h1 * w2a.y + h2 * w2a.z + h3 * w2a.w
                       + h4 * w2b.x + h5 * w2b.y + h6 * w2b.z + h7 * w2b.w;

            part += __shfl_xor_sync(0xffffffffu, part, 8);
            part += __shfl_xor_sync(0xffffffffu, part, 4);
            part += __shfl_xor_sync(0xffffffffu, part, 2);
            part += __shfl_xor_sync(0xffffffffu, part, 1);

            if (tc == 0 && e < E)
                out[e] = part + b2v;
        }
    }
}

// ---------------------------------------------------------------------------
extern "C" void kernel_launch(void* const* d_in, const int* in_sizes, int n_in,
                              void* d_out, int out_size) {
    const float* z   = (const float*)d_in[0];
    const int*   eli = (const int*)d_in[1];      // int32 (JAX canonicalized)
    const float* ea  = (const float*)d_in[2];
    const float* W1  = (const float*)d_in[3];
    const float* b1  = (const float*)d_in[4];
    const float* W2  = (const float*)d_in[5];
    const float* b2  = (const float*)d_in[6];
    float* out = (float*)d_out;

    int M = in_sizes[0] / NODE_DIM;   // 100000
    int E = out_size;                 // 1000000

    cudaFuncSetAttribute(gemm_tc_kernel,
                         cudaFuncAttributeMaxDynamicSharedMemorySize, GSMEM);

    conv_z_kernel<<<2048, 256>>>(z, M * NODE_DIM);
    conv_B_kernel<<<256, 256>>>(W1);

    int gblocks = (M + 127) / 128;
    gemm_tc_kernel<<<gblocks, 256, GSMEM>>>(M);

    int ntiles = (E + TE - 1) / TE;
    int nblk = ntiles < 592 ? ntiles : 592;
    edge_kernel<<<nblk, 256>>>(eli, ea, W1, b1, W2, b2, out, E);
}

// round 6
// speedup vs baseline: 3.2151x; 1.6569x over previous
#include <cuda_runtime.h>
#include <cuda_bf16.h>
#include <cstdint>

#define NODE_DIM 256
#define HIDDEN   128
#define MAX_NODES 100000

// ---------------- device scratch ----------------
__device__ float         g_PQ [(size_t)MAX_NODES * 256];   // P(+b1)|Q per node
__device__ __nv_bfloat16 g_Bhi[256 * 256];                  // B[n][k] = W1ab[k][n]
__device__ __nv_bfloat16 g_Blo[256 * 256];

// ---------------- helpers ----------------
__device__ __forceinline__ uint32_t smem_u32(const void* p) {
    uint32_t a;
    asm("{ .reg .u64 t; cvta.to.shared.u64 t, %1; cvt.u32.u64 %0, t; }" : "=r"(a) : "l"(p));
    return a;
}
__device__ __forceinline__ void ldsm4(uint32_t* r, uint32_t addr) {
    asm volatile("ldmatrix.sync.aligned.m8n8.x4.shared.b16 {%0,%1,%2,%3}, [%4];"
        : "=r"(r[0]), "=r"(r[1]), "=r"(r[2]), "=r"(r[3]) : "r"(addr));
}
__device__ __forceinline__ void mma_bf16(float* d, const uint32_t* a, const uint32_t* b) {
    asm volatile("mma.sync.aligned.m16n8k16.row.col.f32.bf16.bf16.f32 "
        "{%0,%1,%2,%3}, {%4,%5,%6,%7}, {%8,%9}, {%0,%1,%2,%3};"
        : "+f"(d[0]), "+f"(d[1]), "+f"(d[2]), "+f"(d[3])
        : "r"(a[0]), "r"(a[1]), "r"(a[2]), "r"(a[3]), "r"(b[0]), "r"(b[1]));
}
#define SW128(o) ((o) ^ (((o) >> 3) & 0x70))

union BP4 { __nv_bfloat16 b[4]; uint2 u; };
__device__ __forceinline__ void split4(const float4& v, uint2& uh, uint2& ul) {
    float x[4] = {v.x, v.y, v.z, v.w};
    BP4 hi, lo;
    #pragma unroll
    for (int t = 0; t < 4; t++) {
        hi.b[t] = __float2bfloat16(x[t]);
        lo.b[t] = __float2bfloat16(x[t] - __bfloat162float(hi.b[t]));
    }
    uh = hi.u; ul = lo.u;
}

// ---------------------------------------------------------------------------
// conv_B: B[n][k] bf16 hi/lo.  n<128 -> W1[k][n]; n>=128 -> W1[256+k][n-128]
// ---------------------------------------------------------------------------
__global__ void conv_B_kernel(const float* __restrict__ W1) {
    int idx = blockIdx.x * blockDim.x + threadIdx.x;   // 0..65535
    int n = idx >> 8, k = idx & 255;
    float w = (n < HIDDEN) ? W1[(size_t)k * HIDDEN + n]
                           : W1[(size_t)(256 + k) * HIDDEN + (n - HIDDEN)];
    __nv_bfloat16 hi = __float2bfloat16(w);
    __nv_bfloat16 lo = __float2bfloat16(w - __bfloat162float(hi));
    g_Bhi[idx] = hi;
    g_Blo[idx] = lo;
}

// ---------------------------------------------------------------------------
// Phase 1: PQ = z @ [W1a|W1b] via mma.sync bf16 3-term split, fused z convert.
// b1 is folded into the P half here.
// ---------------------------------------------------------------------------
#define SA_HI 0
#define SA_LO 16384
#define SB_HI 32768
#define SB_LO 49152
#define GSMEM 65536

__global__ __launch_bounds__(256, 2) void gemm_tc_kernel(
    const float* __restrict__ z, const float* __restrict__ b1, int M)
{
    extern __shared__ char smem[];
    const uint32_t sb = smem_u32(smem);
    const int tid  = threadIdx.x;
    const int warp = tid >> 5;
    const int lane = tid & 31;
    const int m0   = blockIdx.x * 128;

    const uint32_t a_row  = warp * 16 + ((lane >> 3) & 1) * 8 + (lane & 7);
    const uint32_t a_koff = (lane >> 4) * 16;
    const uint32_t b_rowi = ((lane >> 4) & 1) * 8 + (lane & 7);
    const uint32_t b_koff = ((lane >> 3) & 1) * 16;

    #pragma unroll 1
    for (int nh = 0; nh < 2; nh++) {
        float acc[16][4];
        #pragma unroll
        for (int i = 0; i < 16; i++)
            #pragma unroll
            for (int j = 0; j < 4; j++) acc[i][j] = 0.f;

        #pragma unroll 1
        for (int ch = 0; ch < 4; ch++) {
            const int kc = ch * 64;
            __syncthreads();
            // A: z fp32 (128 x 64), split to hi/lo in-kernel, SW128 rows
            #pragma unroll
            for (int j = 0; j < 8; j++) {
                int id = j * 256 + tid;        // 0..2047 float4 slots
                int r = id >> 4, c = id & 15;
                float4 v = make_float4(0.f, 0.f, 0.f, 0.f);
                if (m0 + r < M)
                    v = *(const float4*)(z + (size_t)(m0 + r) * 256 + kc + c * 4);
                uint2 uh, ul;
                split4(v, uh, ul);
                uint32_t so = SW128((uint32_t)(r * 128 + c * 8));
                *(uint2*)(smem + SA_HI + so) = uh;
                *(uint2*)(smem + SA_LO + so) = ul;
            }
            // B tiles: 128 n-rows (this half) x 64 bf16
            #pragma unroll
            for (int j = 0; j < 4; j++) {
                int id = j * 256 + tid;
                int r = id >> 3, c = id & 7;
                size_t off = (size_t)(nh * 128 + r) * 256 + kc + c * 8;
                uint4 vh = *(const uint4*)(g_Bhi + off);
                uint4 vl = *(const uint4*)(g_Blo + off);
                uint32_t so = SW128((uint32_t)(r * 128 + c * 16));
                *(uint4*)(smem + SB_HI + so) = vh;
                *(uint4*)(smem + SB_LO + so) = vl;
            }
            __syncthreads();

            #pragma unroll
            for (int kt = 0; kt < 4; kt++) {
                uint32_t ah[4], al[4];
                uint32_t aoff = SW128(a_row * 128 + kt * 32 + a_koff);
                ldsm4(ah, sb + SA_HI + aoff);
                ldsm4(al, sb + SA_LO + aoff);
                #pragma unroll
                for (int ntp = 0; ntp < 8; ntp++) {
                    uint32_t boff = SW128((ntp * 16 + b_rowi) * 128 + kt * 32 + b_koff);
                    uint32_t bh[4], bl[4];
                    ldsm4(bh, sb + SB_HI + boff);
                    ldsm4(bl, sb + SB_LO + boff);
                    mma_bf16(acc[2 * ntp],     ah, bh);
                    mma_bf16(acc[2 * ntp],     ah, bl);
                    mma_bf16(acc[2 * ntp],     al, bh);
                    mma_bf16(acc[2 * ntp + 1], ah, bh + 2);
                    mma_bf16(acc[2 * ntp + 1], ah, bl + 2);
                    mma_bf16(acc[2 * ntp + 1], al, bh + 2);
                }
            }
        }

        // Epilogue: +b1 on P half, write to g_PQ
        const int r0 = m0 + warp * 16 + (lane >> 2);
        const int cb = 2 * (lane & 3);
        #pragma unroll
        for (int nt = 0; nt < 16; nt++) {
            int ncol = cb + nt * 8;                 // col within this half
            float2 bb = make_float2(0.f, 0.f);
            if (nh == 0) bb = __ldg((const float2*)(b1 + ncol));
            int n0 = nh * 128 + ncol;
            if (r0 < M)
                *(float2*)(g_PQ + (size_t)r0 * 256 + n0) =
                    make_float2(acc[nt][0] + bb.x, acc[nt][1] + bb.y);
            if (r0 + 8 < M)
                *(float2*)(g_PQ + (size_t)(r0 + 8) * 256 + n0) =
                    make_float2(acc[nt][2] + bb.x, acc[nt][3] + bb.y);
        }
        __syncthreads();
    }
}

// ---------------------------------------------------------------------------
// Phase 2: edge tiles (128 edges). ea@W1c on tensor cores (bf16 3-term,
// in-kernel split), fused gather epilogue (b1 already folded into P).
// Rows padded to 80B (40 bf16) for conflict-free ldmatrix.
// ---------------------------------------------------------------------------
#define TE 128

__global__ __launch_bounds__(256, 2) void edge_kernel(
    const int* __restrict__ eli, const float* __restrict__ ea,
    const float* __restrict__ W1, const float* __restrict__ W2,
    const float* __restrict__ b2, float* __restrict__ out, int E)
{
    __shared__ __align__(16) __nv_bfloat16 sAh[128 * 40];
    __shared__ __align__(16) __nv_bfloat16 sAl[128 * 40];
    __shared__ __align__(16) __nv_bfloat16 sWh[128 * 40];
    __shared__ __align__(16) __nv_bfloat16 sWl[128 * 40];
    __shared__ float sW2[128];
    __shared__ int   sS[TE];
    __shared__ int   sD[TE];

    const int tid  = threadIdx.x;
    const int warp = tid >> 5;
    const int lane = tid & 31;

    // One-time per block: W1c -> sW[n][k] hi/lo, W2 -> smem
    #pragma unroll
    for (int j = 0; j < 16; j++) {
        int id = j * 256 + tid;            // 0..4095
        int k = id >> 7, n = id & 127;
        float w = W1[(size_t)(512 + k) * HIDDEN + n];
        __nv_bfloat16 hi = __float2bfloat16(w);
        sWh[n * 40 + k] = hi;
        sWl[n * 40 + k] = __float2bfloat16(w - __bfloat162float(hi));
    }
    if (tid < 128) sW2[tid] = W2[tid];
    const float b2v = b2[0];

    const uint32_t sbAh = smem_u32(sAh), sbAl = smem_u32(sAl);
    const uint32_t sbWh = smem_u32(sWh), sbWl = smem_u32(sWl);

    const uint32_t a_row  = warp * 16 + ((lane >> 3) & 1) * 8 + (lane & 7);
    const uint32_t a_koff = (lane >> 4) * 16;
    const uint32_t b_rowi = ((lane >> 4) & 1) * 8 + (lane & 7);
    const uint32_t b_koff = ((lane >> 3) & 1) * 16;
    const int cb = 2 * (lane & 3);

    const int ntiles = (E + TE - 1) / TE;

    for (int tile = blockIdx.x; tile < ntiles; tile += gridDim.x) {
        const int e0 = tile * TE;
        __syncthreads();   // protect smem from previous tile's readers

        if (tid < TE) {
            int e = e0 + tid;
            sS[tid] = (e < E) ? eli[e] : 0;
        } else {
            int e = e0 + (tid - TE);
            sD[tid - TE] = (e < E) ? eli[(size_t)E + e] : 0;
        }

        // EA tile fp32 -> bf16 hi/lo, rows of 40 bf16 (k 0..31 data)
        #pragma unroll
        for (int j = 0; j < 4; j++) {
            int id = j * 256 + tid;        // 0..1023 float4 slots
            int e = id >> 3, c4 = id & 7;
            float4 v = make_float4(0.f, 0.f, 0.f, 0.f);
            if (e0 + e < E)
                v = *(const float4*)(ea + (size_t)(e0 + e) * 32 + c4 * 4);
            uint2 uh, ul;
            split4(v, uh, ul);
            *(uint2*)(sAh + e * 40 + c4 * 4) = uh;
            *(uint2*)(sAl + e * 40 + c4 * 4) = ul;
        }
        __syncthreads();

        // Tensor GEMM: D[128e x 128n] = EA @ W1c, 3-term split
        float acc[16][4];
        #pragma unroll
        for (int i = 0; i < 16; i++)
            #pragma unroll
            for (int j = 0; j < 4; j++) acc[i][j] = 0.f;

        #pragma unroll
        for (int kt = 0; kt < 2; kt++) {
            uint32_t ah[4], al[4];
            uint32_t aoff = a_row * 80 + kt * 32 + a_koff;
            ldsm4(ah, sbAh + aoff);
            ldsm4(al, sbAl + aoff);
            #pragma unroll
            for (int ntp = 0; ntp < 8; ntp++) {
                uint32_t boff = (ntp * 16 + b_rowi) * 80 + kt * 32 + b_koff;
                uint32_t bh[4], bl[4];
                ldsm4(bh, sbWh + boff);
                ldsm4(bl, sbWl + boff);
                mma_bf16(acc[2 * ntp],     ah, bh);
                mma_bf16(acc[2 * ntp],     ah, bl);
                mma_bf16(acc[2 * ntp],     al, bh);
                mma_bf16(acc[2 * ntp + 1], ah, bh + 2);
                mma_bf16(acc[2 * ntp + 1], ah, bl + 2);
                mma_bf16(acc[2 * ntp + 1], al, bh + 2);
            }
        }

        // Epilogue: gather P(+b1)/Q, relu, dot W2, quad-reduce
        #pragma unroll
        for (int i = 0; i < 2; i++) {
            int eloc = warp * 16 + (lane >> 2) + 8 * i;
            int e    = e0 + eloc;
            int s    = sS[eloc];
            int d    = sD[eloc];
            const float* pb = g_PQ + (size_t)s * 256;
            const float* qb = g_PQ + (size_t)d * 256 + 128;
            float part = 0.f;
            #pragma unroll
            for (int nt = 0; nt < 16; nt++) {
                int col = nt * 8 + cb;
                float2 p  = __ldg((const float2*)(pb + col));
                float2 q  = __ldg((const float2*)(qb + col));
                float2 w2 = *(const float2*)(&sW2[col]);
                float h0 = fmaxf(acc[nt][2 * i]     + p.x + q.x, 0.f);
                float h1 = fmaxf(acc[nt][2 * i + 1] + p.y + q.y, 0.f);
                part = fmaf(h0, w2.x, fmaf(h1, w2.y, part));
            }
            part += __shfl_xor_sync(0xffffffffu, part, 1);
            part += __shfl_xor_sync(0xffffffffu, part, 2);
            if ((lane & 3) == 0 && e < E)
                out[e] = part + b2v;
        }
    }
}

// ---------------------------------------------------------------------------
extern "C" void kernel_launch(void* const* d_in, const int* in_sizes, int n_in,
                              void* d_out, int out_size) {
    const float* z   = (const float*)d_in[0];
    const int*   eli = (const int*)d_in[1];      // int32 (JAX canonicalized)
    const float* ea  = (const float*)d_in[2];
    const float* W1  = (const float*)d_in[3];
    const float* b1  = (const float*)d_in[4];
    const float* W2  = (const float*)d_in[5];
    const float* b2  = (const float*)d_in[6];
    float* out = (float*)d_out;

    int M = in_sizes[0] / NODE_DIM;   // 100000
    int E = out_size;                 // 1000000

    cudaFuncSetAttribute(gemm_tc_kernel,
                         cudaFuncAttributeMaxDynamicSharedMemorySize, GSMEM);

    conv_B_kernel<<<256, 256>>>(W1);

    int gblocks = (M + 127) / 128;
    gemm_tc_kernel<<<gblocks, 256, GSMEM>>>(z, b1, M);

    int ntiles = (E + TE - 1) / TE;
    int nblk = ntiles < 296 ? ntiles : 296;
    edge_kernel<<<nblk, 256>>>(eli, ea, W1, W2, b2, out, E);
}